// round 16
// baseline (speedup 1.0000x reference)
#include <cuda_runtime.h>
#include <math.h>
#include <stdint.h>

// Geometry: point_1 (96000,3) feat_1 (96000,128); point_2 (24000,3)
// feat_2 (24000,256); B=8 -> 12000 queries / 3000 points per cloud.
#define B_CONST     8
#define N_TOT_MAX   96000
#define M_TOT_MAX   24000
#define OUTP        128
#define MP_MAX      1500      // point PAIRS per cloud

// ---------------- device scratch ------------------------------------------
__device__ float  g_f2[M_TOT_MAX * OUTP];
__device__ float4 g_ptsA[M_TOT_MAX / 2];   // (-2x0,-2x1,-2y0,-2y1)
__device__ float4 g_ptsB[M_TOT_MAX / 2];   // (-2z0,-2z1, pp0, pp1)
__device__ int    g_idx[N_TOT_MAX * 3];
__device__ float  g_w [N_TOT_MAX * 3];

// ---------------- frozen numerics (bit-exact vs reference) ----------------
__device__ __forceinline__ float sq3(float x, float y, float z) {
    return __fmaf_rn(x, x, __fmaf_rn(y, y, __fmul_rn(z, z)));
}

// ---------------- packed f32x2 helpers ------------------------------------
__device__ __forceinline__ uint64_t bcast2(float v) {
    uint64_t r; uint32_t u = __float_as_uint(v);
    asm("mov.b64 %0, {%1, %1};" : "=l"(r) : "r"(u));
    return r;
}
__device__ __forceinline__ uint64_t mul2(uint64_t a, uint64_t b) {
    uint64_t d; asm("mul.rn.f32x2 %0, %1, %2;" : "=l"(d) : "l"(a), "l"(b));
    return d;
}
__device__ __forceinline__ uint64_t fma2(uint64_t a, uint64_t b, uint64_t c) {
    uint64_t d; asm("fma.rn.f32x2 %0, %1, %2, %3;" : "=l"(d) : "l"(a), "l"(b), "l"(c));
    return d;
}
__device__ __forceinline__ uint64_t add2(uint64_t a, uint64_t b) {
    uint64_t d; asm("add.rn.f32x2 %0, %1, %2;" : "=l"(d) : "l"(a), "l"(b));
    return d;
}
__device__ __forceinline__ void unpack2(uint64_t v, float& lo, float& hi) {
    asm("mov.b64 {%0, %1}, %2;" : "=f"(lo), "=f"(hi) : "l"(v));
}

// ---------------- pack points (negated-doubled pair layout) ---------------
__global__ void pack_pts_kernel(const float* __restrict__ p2, int m_pairs) {
    int i = blockIdx.x * blockDim.x + threadIdx.x;
    if (i < m_pairs) {
        float x0 = p2[6 * i + 0], y0 = p2[6 * i + 1], z0 = p2[6 * i + 2];
        float x1 = p2[6 * i + 3], y1 = p2[6 * i + 4], z1 = p2[6 * i + 5];
        g_ptsA[i] = make_float4(-2.0f * x0, -2.0f * x1, -2.0f * y0, -2.0f * y1);
        g_ptsB[i] = make_float4(-2.0f * z0, -2.0f * z1, sq3(x0, y0, z0), sq3(x1, y1, z1));
    }
}

// ---------------- exact 3-NN + IDW body (f32x2) ---------------------------
// BYTE-IDENTICAL numerics to the round-11/15 passing kernels; relocated into
// a __device__ body over dynamic smem so it can co-launch with gemm2.
__device__ __noinline__ void knn_body(char* smem_raw,
                                      const float* __restrict__ q_pts,
                                      int bid, int n_per, int m_pairs,
                                      int bpb, int qpb) {
    float4* spA = reinterpret_cast<float4*>(smem_raw);
    float4* spB = spA + MP_MAX;
    int batch = bid / bpb;
    int bb    = bid % bpb;
    int tid = threadIdx.x;

    for (int i = tid; i < m_pairs; i += blockDim.x) {
        spA[i] = g_ptsA[batch * m_pairs + i];
        spB[i] = g_ptsB[batch * m_pairs + i];
    }
    __syncthreads();

    int ql = bb * qpb + tid;
    if (tid >= qpb || ql >= n_per) return;
    int qg = batch * n_per + ql;

    float qx = q_pts[3 * qg + 0];
    float qy = q_pts[3 * qg + 1];
    float qz = q_pts[3 * qg + 2];
    float qq = sq3(qx, qy, qz);

    uint64_t qx2 = bcast2(qx), qy2 = bcast2(qy), qz2 = bcast2(qz);
    uint64_t qq2 = bcast2(qq);

    uint32_t sA = (uint32_t)__cvta_generic_to_shared(spA);
    uint32_t sB = (uint32_t)__cvta_generic_to_shared(spB);

    float b0v = INFINITY, b1v = INFINITY, b2v = INFINITY;
    int   b0i = 0, b1i = 0, b2i = 0;

    // m_pairs = 1500 = 375 * 4 (exact)
#pragma unroll 1
    for (int jp0 = 0; jp0 < m_pairs; jp0 += 4) {
        float dv[8];
        float cmin;
#pragma unroll
        for (int u = 0; u < 4; u++) {
            uint32_t off = (uint32_t)(jp0 + u) * 16u;
            uint64_t px2, py2, pz2, pw2;
            asm("ld.shared.v2.u64 {%0, %1}, [%2];"
                : "=l"(px2), "=l"(py2) : "r"(sA + off));
            asm("ld.shared.v2.u64 {%0, %1}, [%2];"
                : "=l"(pz2), "=l"(pw2) : "r"(sB + off));
            uint64_t dotn = fma2(qz2, pz2, fma2(qy2, py2, mul2(qx2, px2)));
            uint64_t t    = add2(qq2, pw2);
            uint64_t d    = add2(t, dotn);
            float dlo, dhi;
            unpack2(d, dlo, dhi);
            dv[2 * u]     = dlo;
            dv[2 * u + 1] = dhi;
            float m = fminf(dlo, dhi);
            cmin = (u == 0) ? m : fminf(cmin, m);
        }
        if (cmin < b2v) {
#pragma unroll
            for (int v = 0; v < 8; v++) {
                float d = dv[v];
                if (d < b2v) {
                    int j = jp0 * 2 + v;
                    if (d < b1v) {
                        b2v = b1v; b2i = b1i;
                        if (d < b0v) { b1v = b0v; b1i = b0i; b0v = d; b0i = j; }
                        else         { b1v = d;  b1i = j; }
                    } else {
                        b2v = d; b2i = j;
                    }
                }
            }
        }
    }

    float d0 = fmaxf(b0v, 0.0f);
    float d1 = fmaxf(b1v, 0.0f);
    float d2 = fmaxf(b2v, 0.0f);
    float r0 = __fdiv_rn(1.0f, __fadd_rn(d0, 1e-8f));
    float r1 = __fdiv_rn(1.0f, __fadd_rn(d1, 1e-8f));
    float r2 = __fdiv_rn(1.0f, __fadd_rn(d2, 1e-8f));
    float s = __fadd_rn(__fadd_rn(r0, r1), r2);
    int m_per = m_pairs * 2;
    g_w[qg * 3 + 0] = __fdiv_rn(r0, s);
    g_w[qg * 3 + 1] = __fdiv_rn(r1, s);
    g_w[qg * 3 + 2] = __fdiv_rn(r2, s);
    g_idx[qg * 3 + 0] = batch * m_per + b0i;
    g_idx[qg * 3 + 1] = batch * m_per + b1i;
    g_idx[qg * 3 + 2] = batch * m_per + b2i;
}

// ---------------- gemm2 body (BM=64, K=256, no gather) --------------------
// BYTE-IDENTICAL numerics to the frozen round-11 GEMM (sequential
// ascending-k fma per output); relocated over dynamic smem.
#define GAS(buf, k, r)  As_[((buf) * 16 + (k)) * 68 + (r)]
#define GBS(buf, k, n)  Bs_[((buf) * 16 + (k)) * 128 + (n)]

__device__ __noinline__ void gemm2_body(char* smem_raw, int bid,
                                        const float* __restrict__ X,
                                        const float* __restrict__ Wt,
                                        const float* __restrict__ bb,
                                        const float* __restrict__ gg,
                                        const float* __restrict__ bet,
                                        const float* __restrict__ mu,
                                        const float* __restrict__ var,
                                        float* __restrict__ out, int M) {
    constexpr int K = 256;
    float* As_ = reinterpret_cast<float*>(smem_raw);            // 2*16*68
    float* Bs_ = As_ + 2 * 16 * 68;                             // 2*16*128

    int tid = threadIdx.x;
    int tx = tid & 15;
    int ty = tid >> 4;
    int m0 = bid * 64;

    float acc[4][8];
#pragma unroll
    for (int r = 0; r < 4; r++)
#pragma unroll
        for (int c = 0; c < 8; c++) acc[r][c] = 0.0f;

    int a_row = tid >> 2;
    int a_k   = (tid & 3) * 4;
    int b_k = tid >> 5;
    int b_n = (tid & 31) * 4;

    int ar0 = m0 + a_row;  if (ar0 >= M) ar0 = M - 1;
    const float* pa0 = X + (size_t)ar0 * K + a_k;

    constexpr int NT = K / 16;

    float4 va0, vb0, vb1;
    va0 = *reinterpret_cast<const float4*>(pa0);
    vb0 = *reinterpret_cast<const float4*>(&Wt[(size_t)b_k * 128 + b_n]);
    vb1 = *reinterpret_cast<const float4*>(&Wt[(size_t)(b_k + 8) * 128 + b_n]);
    {
        float av0[4] = {va0.x, va0.y, va0.z, va0.w};
#pragma unroll
        for (int i = 0; i < 4; i++) GAS(0, a_k + i, a_row) = av0[i];
        *reinterpret_cast<float4*>(&GBS(0, b_k, b_n)) = vb0;
        *reinterpret_cast<float4*>(&GBS(0, b_k + 8, b_n)) = vb1;
    }
    __syncthreads();

    for (int kt = 0; kt < NT; kt++) {
        int buf = kt & 1;
        if (kt + 1 < NT) {
            int ko = (kt + 1) * 16;
            va0 = *reinterpret_cast<const float4*>(pa0 + ko);
            vb0 = *reinterpret_cast<const float4*>(&Wt[(size_t)(ko + b_k) * 128 + b_n]);
            vb1 = *reinterpret_cast<const float4*>(&Wt[(size_t)(ko + b_k + 8) * 128 + b_n]);
        }

#pragma unroll
        for (int kk = 0; kk < 16; kk++) {
            float4 x0 = *reinterpret_cast<const float4*>(&GAS(buf, kk, ty * 4));
            float av[4] = {x0.x, x0.y, x0.z, x0.w};
            float4 y0 = *reinterpret_cast<const float4*>(&GBS(buf, kk, tx * 4));
            float4 y1 = *reinterpret_cast<const float4*>(&GBS(buf, kk, 64 + tx * 4));
            float bv[8] = {y0.x, y0.y, y0.z, y0.w, y1.x, y1.y, y1.z, y1.w};
#pragma unroll
            for (int r = 0; r < 4; r++)
#pragma unroll
                for (int c = 0; c < 8; c++)
                    acc[r][c] = fmaf(av[r], bv[c], acc[r][c]);
        }

        if (kt + 1 < NT) {
            int nb = buf ^ 1;
            float av0[4] = {va0.x, va0.y, va0.z, va0.w};
#pragma unroll
            for (int i = 0; i < 4; i++) GAS(nb, a_k + i, a_row) = av0[i];
            *reinterpret_cast<float4*>(&GBS(nb, b_k, b_n)) = vb0;
            *reinterpret_cast<float4*>(&GBS(nb, b_k + 8, b_n)) = vb1;
            __syncthreads();
        }
    }

    int col0 = tx * 4;
    int col1 = 64 + tx * 4;
    float S[8], T[8];
#pragma unroll
    for (int c = 0; c < 8; c++) {
        int cc = (c < 4) ? (col0 + c) : (col1 + c - 4);
        float sc = gg[cc] * rsqrtf(var[cc] + 1e-5f);
        S[c] = sc;
        T[c] = fmaf(bb[cc] - mu[cc], sc, bet[cc]);
    }
#pragma unroll
    for (int r = 0; r < 4; r++) {
        int row = m0 + ty * 4 + r;
        if (row < M) {
            float o[8];
#pragma unroll
            for (int c = 0; c < 8; c++)
                o[c] = fmaxf(fmaf(acc[r][c], S[c], T[c]), 0.0f);
            float4 w0 = make_float4(o[0], o[1], o[2], o[3]);
            float4 w1 = make_float4(o[4], o[5], o[6], o[7]);
            *reinterpret_cast<float4*>(&out[(size_t)row * 128 + col0]) = w0;
            *reinterpret_cast<float4*>(&out[(size_t)row * 128 + col1]) = w1;
        }
    }
}

// ---------------- fused knn + gemm2 launch --------------------------------
// Even blockIdx -> knn block (376), odd -> gemm2 block (375). Interleaved so
// both populations are co-resident on every SM: knn's idle issue slots are
// filled by gemm2's FFMA stream and vice versa (serial 48+120 -> blended).
__global__ void __launch_bounds__(256, 3)
fused_knn_gemm2_kernel(const float* __restrict__ q_pts,
                       int n_per, int m_pairs, int bpb, int qpb,
                       const float* __restrict__ X2, const float* __restrict__ W2,
                       const float* __restrict__ bb2, const float* __restrict__ gg2,
                       const float* __restrict__ bet2, const float* __restrict__ mu2,
                       const float* __restrict__ var2, float* __restrict__ f2out,
                       int M2) {
    extern __shared__ __align__(16) char smem_raw[];
    int b = blockIdx.x;
    if (b & 1) {
        gemm2_body(smem_raw, (b - 1) >> 1, X2, W2, bb2, gg2, bet2, mu2, var2,
                   f2out, M2);
    } else {
        knn_body(smem_raw, q_pts, b >> 1, n_per, m_pairs, bpb, qpb);
    }
}

// ---------------- exact-fp32 GEMM + fused BN/ReLU + gather (gemm1) --------
// FROZEN (round 11, ~92% of FFMA rt=2 roofline). BM=128.
template <int K, int BM, int MB, bool GATHER>
__global__ void __launch_bounds__(256, MB)
gemm_bn_relu_kernel(const float* __restrict__ X, const float* __restrict__ Wt,
                    const float* __restrict__ bb, const float* __restrict__ gg,
                    const float* __restrict__ bet, const float* __restrict__ mu,
                    const float* __restrict__ var, float* __restrict__ out,
                    int M) {
    constexpr int RPT = BM / 16;
    __shared__ __align__(16) float As[2][16][BM + 4];
    __shared__ __align__(16) float Bs[2][16][128];

    int tid = threadIdx.x;
    int tx = tid & 15;
    int ty = tid >> 4;
    int m0 = blockIdx.x * BM;

    float acc[RPT][8];
#pragma unroll
    for (int r = 0; r < RPT; r++)
#pragma unroll
        for (int c = 0; c < 8; c++) acc[r][c] = 0.0f;

    int a_row = tid >> 2;
    int a_k   = (tid & 3) * 4;
    int b_k = tid >> 5;
    int b_n = (tid & 31) * 4;

    int ar0 = m0 + a_row;       if (ar0 >= M) ar0 = M - 1;
    const float* pa0 = X + (size_t)ar0 * K + a_k;
    const float* pa1 = pa0;
    if (BM == 128) {
        int ar1 = m0 + 64 + a_row;  if (ar1 >= M) ar1 = M - 1;
        pa1 = X + (size_t)ar1 * K + a_k;
    }

    constexpr int NT = K / 16;

    float4 va0, va1, vb0, vb1;
    va0 = *reinterpret_cast<const float4*>(pa0);
    if (BM == 128) va1 = *reinterpret_cast<const float4*>(pa1);
    vb0 = *reinterpret_cast<const float4*>(&Wt[(size_t)b_k * 128 + b_n]);
    vb1 = *reinterpret_cast<const float4*>(&Wt[(size_t)(b_k + 8) * 128 + b_n]);
    {
        float av0[4] = {va0.x, va0.y, va0.z, va0.w};
#pragma unroll
        for (int i = 0; i < 4; i++) As[0][a_k + i][a_row] = av0[i];
        if (BM == 128) {
            float av1[4] = {va1.x, va1.y, va1.z, va1.w};
#pragma unroll
            for (int i = 0; i < 4; i++) As[0][a_k + i][64 + a_row] = av1[i];
        }
        *reinterpret_cast<float4*>(&Bs[0][b_k][b_n]) = vb0;
        *reinterpret_cast<float4*>(&Bs[0][b_k + 8][b_n]) = vb1;
    }
    __syncthreads();

    for (int kt = 0; kt < NT; kt++) {
        int buf = kt & 1;
        if (kt + 1 < NT) {
            int ko = (kt + 1) * 16;
            va0 = *reinterpret_cast<const float4*>(pa0 + ko);
            if (BM == 128) va1 = *reinterpret_cast<const float4*>(pa1 + ko);
            vb0 = *reinterpret_cast<const float4*>(&Wt[(size_t)(ko + b_k) * 128 + b_n]);
            vb1 = *reinterpret_cast<const float4*>(&Wt[(size_t)(ko + b_k + 8) * 128 + b_n]);
        }

#pragma unroll
        for (int kk = 0; kk < 16; kk++) {
            float av[RPT];
#pragma unroll
            for (int r = 0; r < RPT; r += 4) {
                float4 x0 = *reinterpret_cast<const float4*>(&As[buf][kk][ty * RPT + r]);
                av[r] = x0.x; av[r + 1] = x0.y; av[r + 2] = x0.z; av[r + 3] = x0.w;
            }
            float4 y0 = *reinterpret_cast<const float4*>(&Bs[buf][kk][tx * 4]);
            float4 y1 = *reinterpret_cast<const float4*>(&Bs[buf][kk][64 + tx * 4]);
            float bv[8] = {y0.x, y0.y, y0.z, y0.w, y1.x, y1.y, y1.z, y1.w};
#pragma unroll
            for (int r = 0; r < RPT; r++)
#pragma unroll
                for (int c = 0; c < 8; c++)
                    acc[r][c] = fmaf(av[r], bv[c], acc[r][c]);
        }

        if (kt + 1 < NT) {
            int nb = buf ^ 1;
            float av0[4] = {va0.x, va0.y, va0.z, va0.w};
#pragma unroll
            for (int i = 0; i < 4; i++) As[nb][a_k + i][a_row] = av0[i];
            if (BM == 128) {
                float av1[4] = {va1.x, va1.y, va1.z, va1.w};
#pragma unroll
                for (int i = 0; i < 4; i++) As[nb][a_k + i][64 + a_row] = av1[i];
            }
            *reinterpret_cast<float4*>(&Bs[nb][b_k][b_n]) = vb0;
            *reinterpret_cast<float4*>(&Bs[nb][b_k + 8][b_n]) = vb1;
            __syncthreads();
        }
    }

    int col0 = tx * 4;
    int col1 = 64 + tx * 4;
    float S[8], T[8];
#pragma unroll
    for (int c = 0; c < 8; c++) {
        int cc = (c < 4) ? (col0 + c) : (col1 + c - 4);
        float sc = gg[cc] * rsqrtf(var[cc] + 1e-5f);
        S[c] = sc;
        T[c] = fmaf(bb[cc] - mu[cc], sc, bet[cc]);
    }
#pragma unroll
    for (int r = 0; r < RPT; r++) {
        int row = m0 + ty * RPT + r;
        if (row < M) {
            float o[8];
#pragma unroll
            for (int c = 0; c < 8; c++)
                o[c] = fmaxf(fmaf(acc[r][c], S[c], T[c]), 0.0f);
            if (GATHER) {
#pragma unroll
                for (int t = 0; t < 3; t++) {
                    int id = g_idx[row * 3 + t];
                    float w = g_w[row * 3 + t];
                    const float* f = &g_f2[(size_t)id * 128];
                    float4 f0 = *reinterpret_cast<const float4*>(f + col0);
                    float4 f1 = *reinterpret_cast<const float4*>(f + col1);
                    o[0] = fmaf(w, f0.x, o[0]);
                    o[1] = fmaf(w, f0.y, o[1]);
                    o[2] = fmaf(w, f0.z, o[2]);
                    o[3] = fmaf(w, f0.w, o[3]);
                    o[4] = fmaf(w, f1.x, o[4]);
                    o[5] = fmaf(w, f1.y, o[5]);
                    o[6] = fmaf(w, f1.z, o[6]);
                    o[7] = fmaf(w, f1.w, o[7]);
                }
            }
            float4 w0 = make_float4(o[0], o[1], o[2], o[3]);
            float4 w1 = make_float4(o[4], o[5], o[6], o[7]);
            *reinterpret_cast<float4*>(&out[(size_t)row * 128 + col0]) = w0;
            *reinterpret_cast<float4*>(&out[(size_t)row * 128 + col1]) = w1;
        }
    }
}

// ---------------- launch --------------------------------------------------
extern "C" void kernel_launch(void* const* d_in, const int* in_sizes, int n_in,
                              void* d_out, int out_size) {
    const float* point1 = (const float*)d_in[0];
    const float* feat1  = (const float*)d_in[1];
    const float* point2 = (const float*)d_in[2];
    const float* feat2  = (const float*)d_in[3];
    const float* W1  = (const float*)d_in[4];
    const float* b1  = (const float*)d_in[5];
    const float* g1  = (const float*)d_in[6];
    const float* be1 = (const float*)d_in[7];
    const float* mu1 = (const float*)d_in[8];
    const float* v1  = (const float*)d_in[9];
    const float* W2  = (const float*)d_in[10];
    const float* b2  = (const float*)d_in[11];
    const float* g2  = (const float*)d_in[12];
    const float* be2 = (const float*)d_in[13];
    const float* mu2 = (const float*)d_in[14];
    const float* v2  = (const float*)d_in[15];

    int n_tot = in_sizes[0] / 3;           // 96000
    int m_tot = in_sizes[2] / 3;           // 24000
    int n_per = n_tot / B_CONST;           // 12000
    int m_pairs = (m_tot / B_CONST) / 2;   // 1500

    float* f2 = nullptr;
    cudaGetSymbolAddress((void**)&f2, g_f2);

    const int FUSED_SMEM = MP_MAX * 2 * 16;            // 48000 (knn need)
    static int smem_set = 0;
    if (!smem_set) {
        cudaFuncSetAttribute(fused_knn_gemm2_kernel,
                             cudaFuncAttributeMaxDynamicSharedMemorySize,
                             FUSED_SMEM);
        smem_set = 1;
    }

    // 1) pack coarse points
    int tot_pairs = m_tot / 2;
    pack_pts_kernel<<<(tot_pairs + 255) / 256, 256>>>(point2, tot_pairs);

    // 2) fused: knn (376 even blocks) + gemm2 (375 odd blocks)
    int bpb = 47, qpb = 256;
    int knn_blocks  = B_CONST * bpb;       // 376
    int gemm_blocks = m_tot / 64;          // 375
    fused_knn_gemm2_kernel<<<knn_blocks + gemm_blocks, 256, FUSED_SMEM>>>(
        point1, n_per, m_pairs, bpb, qpb,
        feat2, W2, b2, g2, be2, mu2, v2, f2, m_tot);

    // 3) dense1 + BN + ReLU + gather-add -> out (BM=128)
    gemm_bn_relu_kernel<128, 128, 2, true><<<(n_tot + 127) / 128, 256>>>(
        feat1, W1, b1, g1, be1, mu1, v1, (float*)d_out, n_tot);
}